// round 4
// baseline (speedup 1.0000x reference)
#include <cuda_runtime.h>

// Reference semantics: image (B,M,N,2) raw-reinterpreted as (2B, M, N) planes;
// flow2[p] = flow[p>>1]; out_flat[p*MN + y*N + x] = bilinear(view[p], x+dx, y+dy)
// with zero outside bounds. One thread per (b,y,x) handles planes 2b and 2b+1
// (they share the flow vector and bilinear weights).

#define MM 384
#define NN 384
#define MN (MM * NN)

__global__ __launch_bounds__(256) void warp_kernel(
    const float*  __restrict__ image,  // 2B*MN floats (raw)
    const float2* __restrict__ flow,   // B*MN float2
    float*        __restrict__ out,    // 2B*MN floats (raw)
    int total)                         // B*MN
{
    int idx = blockIdx.x * blockDim.x + threadIdx.x;
    if (idx >= total) return;

    int x = idx % NN;
    int t = idx / NN;
    int y = t % MM;
    int b = t / MM;

    float2 f = __ldg(&flow[idx]);
    float xs = (float)x + f.x;
    float ys = (float)y + f.y;

    float x0f = floorf(xs);
    float y0f = floorf(ys);
    float wx = xs - x0f;
    float wy = ys - y0f;
    int x0 = (int)x0f;
    int y0 = (int)y0f;
    int x1 = x0 + 1;
    int y1 = y0 + 1;

    float w00 = (1.0f - wy) * (1.0f - wx);
    float w01 = (1.0f - wy) * wx;
    float w10 = wy * (1.0f - wx);
    float w11 = wy * wx;

    bool vx0 = (x0 >= 0) & (x0 < NN);
    bool vx1 = (x1 >= 0) & (x1 < NN);
    bool vy0 = (y0 >= 0) & (y0 < MM);
    bool vy1 = (y1 >= 0) & (y1 < MM);

    const float* pA = image + (size_t)(2 * b) * MN;   // plane 2b
    const float* pB = pA + MN;                        // plane 2b+1

    float accA = 0.0f, accB = 0.0f;

    if (vy0 & vx0) {
        int o = y0 * NN + x0;
        accA += __ldg(pA + o) * w00;
        accB += __ldg(pB + o) * w00;
    }
    if (vy0 & vx1) {
        int o = y0 * NN + x1;
        accA += __ldg(pA + o) * w01;
        accB += __ldg(pB + o) * w01;
    }
    if (vy1 & vx0) {
        int o = y1 * NN + x0;
        accA += __ldg(pA + o) * w10;
        accB += __ldg(pB + o) * w10;
    }
    if (vy1 & vx1) {
        int o = y1 * NN + x1;
        accA += __ldg(pA + o) * w11;
        accB += __ldg(pB + o) * w11;
    }

    int po = y * NN + x;
    out[(size_t)(2 * b) * MN + po] = accA;
    out[(size_t)(2 * b) * MN + MN + po] = accB;
}

extern "C" void kernel_launch(void* const* d_in, const int* in_sizes, int n_in,
                              void* d_out, int out_size)
{
    const float*  image = (const float*)d_in[0];
    const float2* flow  = (const float2*)d_in[1];
    float* out = (float*)d_out;

    int total = out_size / 2;  // B*M*N (out_size = 2B*M*N floats)
    int threads = 256;
    int blocks = (total + threads - 1) / threads;
    warp_kernel<<<blocks, threads>>>(image, flow, out, total);
}

// round 5
// speedup vs baseline: 1.1246x; 1.1246x over previous
#include <cuda_runtime.h>

// Reference semantics: image (B,M,N,2) raw-reinterpreted as (2B, M, N) planes;
// flow2[p] = flow[p>>1]; out_flat[p*MN + y*N + x] = bilinear(view[p], x+dx, y+dy),
// zero outside bounds. One thread per (b,y,x) handles planes 2b and 2b+1.
// Branch-free (masked weights, clamped addrs), 2 pixels per thread for ILP.

#define MM 384
#define NN 384
#define MN (MM * NN)

struct Pix {
    int o00, o01, o10, o11;   // clamped corner offsets within plane
    float w00, w01, w10, w11; // masked weights
    size_t baseA;             // plane-A offset (plane B = +MN)
    int po;                   // output offset within plane
};

__device__ __forceinline__ Pix prep(const float2* __restrict__ flow, int idx)
{
    int x = idx % NN;
    int t = idx / NN;
    int y = t % MM;
    int b = t / MM;

    float2 f = __ldg(&flow[idx]);
    float xs = (float)x + f.x;
    float ys = (float)y + f.y;

    float x0f = floorf(xs);
    float y0f = floorf(ys);
    float wx = xs - x0f;
    float wy = ys - y0f;
    int x0 = (int)x0f;
    int y0 = (int)y0f;
    int x1 = x0 + 1;
    int y1 = y0 + 1;

    // validity folded into 1-D weight factors
    float wxm0 = ((unsigned)x0 < (unsigned)NN) ? (1.0f - wx) : 0.0f;
    float wxm1 = ((unsigned)x1 < (unsigned)NN) ? wx : 0.0f;
    float wym0 = ((unsigned)y0 < (unsigned)MM) ? (1.0f - wy) : 0.0f;
    float wym1 = ((unsigned)y1 < (unsigned)MM) ? wy : 0.0f;

    int xc0 = min(max(x0, 0), NN - 1);
    int xc1 = min(max(x1, 0), NN - 1);
    int yc0 = min(max(y0, 0), MM - 1);
    int yc1 = min(max(y1, 0), MM - 1);

    Pix p;
    p.o00 = yc0 * NN + xc0;
    p.o01 = yc0 * NN + xc1;
    p.o10 = yc1 * NN + xc0;
    p.o11 = yc1 * NN + xc1;
    p.w00 = wym0 * wxm0;
    p.w01 = wym0 * wxm1;
    p.w10 = wym1 * wxm0;
    p.w11 = wym1 * wxm1;
    p.baseA = (size_t)(2 * b) * MN;
    p.po = y * NN + x;
    return p;
}

__global__ __launch_bounds__(256) void warp_kernel(
    const float*  __restrict__ image,  // 2B*MN floats (raw)
    const float2* __restrict__ flow,   // B*MN float2
    float*        __restrict__ out,    // 2B*MN floats (raw)
    int total)                         // B*MN
{
    int i0 = blockIdx.x * (blockDim.x * 2) + threadIdx.x;
    int i1 = i0 + blockDim.x;
    if (i0 >= total) return;
    bool has1 = (i1 < total);
    // make second pixel safe (degenerate duplicate) so loads stay unconditional
    int i1s = has1 ? i1 : i0;

    Pix a = prep(flow, i0);
    Pix b = prep(flow, i1s);

    const float* pA0 = image + a.baseA;
    const float* pB0 = pA0 + MN;
    const float* pA1 = image + b.baseA;
    const float* pB1 = pA1 + MN;

    // issue all 16 gathers up front (independent) for max MLP
    float a00A = __ldg(pA0 + a.o00), a01A = __ldg(pA0 + a.o01);
    float a10A = __ldg(pA0 + a.o10), a11A = __ldg(pA0 + a.o11);
    float a00B = __ldg(pB0 + a.o00), a01B = __ldg(pB0 + a.o01);
    float a10B = __ldg(pB0 + a.o10), a11B = __ldg(pB0 + a.o11);

    float b00A = __ldg(pA1 + b.o00), b01A = __ldg(pA1 + b.o01);
    float b10A = __ldg(pA1 + b.o10), b11A = __ldg(pA1 + b.o11);
    float b00B = __ldg(pB1 + b.o00), b01B = __ldg(pB1 + b.o01);
    float b10B = __ldg(pB1 + b.o10), b11B = __ldg(pB1 + b.o11);

    float accA0 = a00A * a.w00 + a01A * a.w01 + a10A * a.w10 + a11A * a.w11;
    float accB0 = a00B * a.w00 + a01B * a.w01 + a10B * a.w10 + a11B * a.w11;
    float accA1 = b00A * b.w00 + b01A * b.w01 + b10A * b.w10 + b11A * b.w11;
    float accB1 = b00B * b.w00 + b01B * b.w01 + b10B * b.w10 + b11B * b.w11;

    out[a.baseA + a.po]      = accA0;
    out[a.baseA + MN + a.po] = accB0;
    if (has1) {
        out[b.baseA + b.po]      = accA1;
        out[b.baseA + MN + b.po] = accB1;
    }
}

extern "C" void kernel_launch(void* const* d_in, const int* in_sizes, int n_in,
                              void* d_out, int out_size)
{
    const float*  image = (const float*)d_in[0];
    const float2* flow  = (const float2*)d_in[1];
    float* out = (float*)d_out;

    int total = out_size / 2;  // B*M*N (out_size = 2B*M*N floats)
    int threads = 256;
    int blocks = (total + threads * 2 - 1) / (threads * 2);
    warp_kernel<<<blocks, threads>>>(image, flow, out, total);
}